// round 10
// baseline (speedup 1.0000x reference)
#include <cuda_runtime.h>
#include <cuda_bf16.h>

#define R_     512
#define C_     256
#define H_     200
#define W_     200
#define OUTK   7
#define HW_    (H_*W_)
#define CHUNK  32   // channels per block; warp covers 4 (w + {0,8,16,24})
#define ROWMAX 28   // max unique patch rows (<= 25 in practice)

// ---------------------------------------------------------------------------
// Fused-oy RoIAlign. Grid (512 roi, 8 chunk), chunk slowest -> per-phase
// feature working set (~17 MB) L2-resident (DRAM ~157 MB, compulsory).
//
// Each block streams each unique patch row ONCE per channel (vs ~1.5x
// redundant cross-oy refetch before) and accumulates into all 7 oy bins via
// a dense per-row weight vector w[row][0..6] built in phase 1, using packed
// fma.rn.f32x2 (4 FFMA2 per row per channel).
//
// R9 bug fixed: s_wt is now __align__(16) (it's read via LDS.128).
//
// Lane -> (ox, x-tap): lane = ox*4 + jx (lanes 28..31 duplicate tap 27,
// never store). Epilogue: unpack 7 accumulators, *xw (0.25 folded),
// 4-lane shfl reduce, 7 coalesced per-oy stores.
// ---------------------------------------------------------------------------

__device__ __forceinline__ unsigned long long pack2(float lo, float hi) {
    unsigned long long d;
    asm("mov.b64 %0, {%1, %2};" : "=l"(d) : "f"(lo), "f"(hi));
    return d;
}
__device__ __forceinline__ void fma2(unsigned long long& d,
                                     unsigned long long a,
                                     unsigned long long b) {
    asm("fma.rn.f32x2 %0, %1, %2, %0;" : "+l"(d) : "l"(a), "l"(b));
}
__device__ __forceinline__ float lo2(unsigned long long v) {
    float a, b; asm("mov.b64 {%0, %1}, %2;" : "=f"(a), "=f"(b) : "l"(v)); return a;
}
__device__ __forceinline__ float hi2(unsigned long long v) {
    float a, b; asm("mov.b64 {%0, %1}, %2;" : "=f"(a), "=f"(b) : "l"(v)); return b;
}

__global__ __launch_bounds__(256) void roialign_kernel(
    const float* __restrict__ feat, const float* __restrict__ rois,
    float* __restrict__ out)
{
    int r   = blockIdx.x;
    int ch0 = blockIdx.y * CHUNK;

    __shared__ __align__(16) float s_wt[ROWMAX * 8];  // [row][oy(7)+pad]
    __shared__ int   s_xi[28];
    __shared__ float s_xw[28];
    __shared__ int   s_yidx[28];
    __shared__ float s_ywt[28];
    __shared__ int   s_rmin, s_rcnt, s_boff;

    int tid  = threadIdx.x;
    int lane = tid & 31;
    int warp = tid >> 5;

    if (warp < 2) {                      // warp0: x-taps, warp1: y-taps
        const float* ro = rois + r * 5;
        bool isx = (warp == 0);
        float p1 = (isx ? ro[1] : ro[2]) * 0.25f;
        float p2 = (isx ? ro[3] : ro[4]) * 0.25f;
        float bin = fmaxf(p2 - p1, 1.0f) * (1.0f / (float)OUTK);

        int t   = min(lane, 27);
        int o   = t >> 2;
        int s   = (t >> 1) & 1;
        int tap = t & 1;
        float y = p1 + ((float)o + ((float)s + 0.5f) * 0.5f) * bin;
        bool valid = (y >= -1.0f) && (y <= 200.0f);
        float yc = fminf(fmaxf(y, 0.0f), 199.0f);
        int   yl = (int)floorf(yc);
        int   yh = min(yl + 1, 199);
        float fl = yc - (float)yl;
        float wv = tap ? fl : (1.0f - fl);
        if (!valid) wv = 0.0f;
        int   iv = tap ? yh : yl;

        if (lane < 28) {
            if (isx) { s_xi[lane] = iv;   s_xw[lane] = wv; }
            else     { s_yidx[lane] = iv; s_ywt[lane] = wv; }
        }
        if (!isx) {
            int vmin = (lane < 28) ? iv : 10000;
            int vmax = (lane < 28) ? iv : -1;
            #pragma unroll
            for (int d = 16; d; d >>= 1) {
                vmin = min(vmin, __shfl_xor_sync(0xffffffffu, vmin, d));
                vmax = max(vmax, __shfl_xor_sync(0xffffffffu, vmax, d));
            }
            if (lane == 0) { s_rmin = vmin; s_rcnt = vmax - vmin + 1; }
        }
        if (tid == 0) s_boff = (int)ro[0] * (C_ * HW_);
    }
    __syncthreads();

    // Build dense per-row y-weight table: thread (row, oy) sums matching taps.
    if (tid < ROWMAX * 8) {
        int row = tid >> 3;
        int oy  = tid & 7;
        float w = 0.f;
        if (oy < 7) {
            int tgt = s_rmin + row;
            #pragma unroll
            for (int k = 0; k < 4; k++) {
                int   i = s_yidx[oy * 4 + k];
                float v = s_ywt[oy * 4 + k];
                w += (i == tgt) ? v : 0.f;
            }
        }
        s_wt[tid] = w;
    }
    __syncthreads();

    int l    = min(lane, 27);
    int   xi = s_xi[l];
    float xw = s_xw[l] * 0.25f;          // fold S*S mean
    int rmin = s_rmin;
    int rcnt = s_rcnt;

    const float* fb = feat + s_boff + (size_t)(ch0 + warp) * HW_;
    const float* f1 = fb +  8 * HW_;
    const float* f2 = fb + 16 * HW_;
    const float* f3 = fb + 24 * HW_;

    // accumulators: [channel 0..3][oy-pair 0..3] packed f32x2
    unsigned long long acc[4][4];
    #pragma unroll
    for (int c = 0; c < 4; c++)
        #pragma unroll
        for (int p = 0; p < 4; p++) acc[c][p] = 0ull;

    const float4* wt4 = (const float4*)s_wt;
    int base = rmin * W_ + xi;

    for (int j = 0; j < rcnt; j++, base += W_) {
        float v0 = __ldg(fb + base);
        float v1 = __ldg(f1 + base);
        float v2 = __ldg(f2 + base);
        float v3 = __ldg(f3 + base);
        float4 wlo = wt4[j * 2];
        float4 whi = wt4[j * 2 + 1];
        unsigned long long w01 = pack2(wlo.x, wlo.y);
        unsigned long long w23 = pack2(wlo.z, wlo.w);
        unsigned long long w45 = pack2(whi.x, whi.y);
        unsigned long long w6z = pack2(whi.z, whi.w);  // whi.w == 0
        unsigned long long vv0 = pack2(v0, v0);
        unsigned long long vv1 = pack2(v1, v1);
        unsigned long long vv2 = pack2(v2, v2);
        unsigned long long vv3 = pack2(v3, v3);
        fma2(acc[0][0], vv0, w01); fma2(acc[0][1], vv0, w23);
        fma2(acc[0][2], vv0, w45); fma2(acc[0][3], vv0, w6z);
        fma2(acc[1][0], vv1, w01); fma2(acc[1][1], vv1, w23);
        fma2(acc[1][2], vv1, w45); fma2(acc[1][3], vv1, w6z);
        fma2(acc[2][0], vv2, w01); fma2(acc[2][1], vv2, w23);
        fma2(acc[2][2], vv2, w45); fma2(acc[2][3], vv2, w6z);
        fma2(acc[3][0], vv3, w01); fma2(acc[3][1], vv3, w23);
        fma2(acc[3][2], vv3, w45); fma2(acc[3][3], vv3, w6z);
    }

    // Epilogue: per channel, x-weight, 4-lane reduce, 7 coalesced stores.
    int  ox      = l >> 2;
    bool doStore = (lane < 28) && ((lane & 3) == 0);
    float* ob    = out + ((size_t)r * C_ + ch0 + warp) * (OUTK * OUTK) + ox;

    #pragma unroll
    for (int c = 0; c < 4; c++) {
        float vals[7] = { lo2(acc[c][0]), hi2(acc[c][0]),
                          lo2(acc[c][1]), hi2(acc[c][1]),
                          lo2(acc[c][2]), hi2(acc[c][2]),
                          lo2(acc[c][3]) };
        float* orow = ob + (size_t)(c * 8) * (OUTK * OUTK);
        #pragma unroll
        for (int oy = 0; oy < 7; oy++) {
            float v = vals[oy] * xw;
            v += __shfl_xor_sync(0xffffffffu, v, 1);
            v += __shfl_xor_sync(0xffffffffu, v, 2);
            if (doStore) orow[oy * OUTK] = v;
        }
    }
}

extern "C" void kernel_launch(void* const* d_in, const int* in_sizes, int n_in,
                              void* d_out, int out_size) {
    const float* feat = (const float*)d_in[0];
    const float* rois = (const float*)d_in[1];
    if (n_in >= 2 && in_sizes[0] == R_ * 5) {  // defensive against input order
        feat = (const float*)d_in[1];
        rois = (const float*)d_in[0];
    }
    float* out = (float*)d_out;

    dim3 grid(R_, C_ / CHUNK);   // chunk (y) slowest -> L2 phase blocking
    roialign_kernel<<<grid, 256>>>(feat, rois, out);
}

// round 11
// speedup vs baseline: 1.2553x; 1.2553x over previous
#include <cuda_runtime.h>
#include <cuda_bf16.h>

#define R_     512
#define C_     256
#define H_     200
#define W_     200
#define OUTK   7
#define HW_    (H_*W_)
#define CHUNK  16   // channels per block; 4 groups x 4 channels
#define ROWMAX 28   // max unique patch rows (<= 26)

// ---------------------------------------------------------------------------
// Split-oy fused RoIAlign. Grid (512 roi, 16 chunk), chunk slowest -> per-
// phase working set (~8.5 MB) L2-resident (DRAM ~157 MB compulsory).
//
// Warp w: half = w>>2 (0: oy bins 0-3, 1: oy bins 4-6), group g = w&3,
// channels {g, g+4, g+8, g+12}. Each warp streams only the row range its
// oy bins need (union ~16 rows/ch vs 20.3 in R8, vs 13.4 ideal) and
// accumulates with packed fma.rn.f32x2 into 4 u64 accs (4ch x 2) -- small
// register footprint (the R10 failure was 16 u64 accs -> 72 regs -> occ 34%).
// Halves write disjoint oy outputs; no combine needed.
//
// Lane -> (ox, x-tap): lane = ox*4 + jx (lanes 28..31 duplicate tap 27,
// never store). Per row: 4 LDG + 1 LDS.128 (4 y-weights of this half) +
// 8 FFMA2. Loop unrolled x2 -> 8 LDGs in flight.
// ---------------------------------------------------------------------------

__device__ __forceinline__ unsigned long long pack2(float lo, float hi) {
    unsigned long long d;
    asm("mov.b64 %0, {%1, %2};" : "=l"(d) : "f"(lo), "f"(hi));
    return d;
}
__device__ __forceinline__ void fma2(unsigned long long& d,
                                     unsigned long long a,
                                     unsigned long long b) {
    asm("fma.rn.f32x2 %0, %1, %2, %0;" : "+l"(d) : "l"(a), "l"(b));
}
__device__ __forceinline__ float lo2(unsigned long long v) {
    float a, b; asm("mov.b64 {%0, %1}, %2;" : "=f"(a), "=f"(b) : "l"(v)); return a;
}
__device__ __forceinline__ float hi2(unsigned long long v) {
    float a, b; asm("mov.b64 {%0, %1}, %2;" : "=f"(a), "=f"(b) : "l"(v)); return b;
}

__global__ __launch_bounds__(256) void roialign_kernel(
    const float* __restrict__ feat, const float* __restrict__ rois,
    float* __restrict__ out)
{
    int r   = blockIdx.x;
    int ch0 = blockIdx.y * CHUNK;

    __shared__ __align__(16) float s_wt[ROWMAX * 8];  // [row][oy(7)+pad]
    __shared__ int   s_xi[28];
    __shared__ float s_xw[28];
    __shared__ int   s_yidx[28];
    __shared__ float s_ywt[28];
    __shared__ int   s_rmin, s_boff;
    __shared__ int   s_lo[2], s_hi[2];   // per-half row range (inclusive)

    int tid  = threadIdx.x;
    int lane = tid & 31;
    int warp = tid >> 5;

    if (warp < 2) {                      // warp0: x-taps, warp1: y-taps
        const float* ro = rois + r * 5;
        bool isx = (warp == 0);
        float p1 = (isx ? ro[1] : ro[2]) * 0.25f;
        float p2 = (isx ? ro[3] : ro[4]) * 0.25f;
        float bin = fmaxf(p2 - p1, 1.0f) * (1.0f / (float)OUTK);

        int t   = min(lane, 27);
        int o   = t >> 2;
        int s   = (t >> 1) & 1;
        int tap = t & 1;
        float y = p1 + ((float)o + ((float)s + 0.5f) * 0.5f) * bin;
        bool valid = (y >= -1.0f) && (y <= 200.0f);
        float yc = fminf(fmaxf(y, 0.0f), 199.0f);
        int   yl = (int)floorf(yc);
        int   yh = min(yl + 1, 199);
        float fl = yc - (float)yl;
        float wv = tap ? fl : (1.0f - fl);
        if (!valid) wv = 0.0f;
        int   iv = tap ? yh : yl;

        if (lane < 28) {
            if (isx) { s_xi[lane] = iv;   s_xw[lane] = wv; }
            else     { s_yidx[lane] = iv; s_ywt[lane] = wv; }
        }
        if (!isx && lane == 0) {
            // tap indices are monotone: per-oy min = first tap, max = last.
            // Written by lane 0 after its own store -- but other lanes' values
            // aren't visible yet; so recompute from iv via shfl instead.
        }
        if (!isx) {
            // broadcast boundary taps to lane 0 via shfl (all lanes active)
            int t0  = __shfl_sync(0xffffffffu, iv, 0);    // min of oy0
            int t15 = __shfl_sync(0xffffffffu, iv, 15);   // max of oy3
            int t16 = __shfl_sync(0xffffffffu, iv, 16);   // min of oy4
            int t27 = __shfl_sync(0xffffffffu, iv, 27);   // max of oy6
            if (lane == 0) {
                s_lo[0] = t0;  s_hi[0] = t15;
                s_lo[1] = t16; s_hi[1] = t27;
                s_rmin  = t0;
            }
        }
        if (tid == 0) s_boff = (int)ro[0] * (C_ * HW_);
    }
    __syncthreads();

    // Dense per-row y-weight table: thread (row, oy) sums matching taps.
    if (tid < ROWMAX * 8) {
        int row = tid >> 3;
        int oy  = tid & 7;
        float w = 0.f;
        if (oy < 7) {
            int tgt = s_rmin + row;
            #pragma unroll
            for (int k = 0; k < 4; k++) {
                int   i = s_yidx[oy * 4 + k];
                float v = s_ywt[oy * 4 + k];
                w += (i == tgt) ? v : 0.f;
            }
        }
        s_wt[tid] = w;
    }
    __syncthreads();

    int half  = warp >> 2;               // 0: oy0-3, 1: oy4-6
    int group = warp & 3;                // channel group
    int l     = min(lane, 27);
    int   xi  = s_xi[l];
    float xw  = s_xw[l] * 0.25f;         // fold S*S mean
    int rmin  = s_rmin;
    int hlo   = s_lo[half];
    int hhi   = s_hi[half];

    const float* f0 = feat + s_boff + (size_t)(ch0 + group) * HW_;
    const float* f1 = f0 +  4 * HW_;
    const float* f2 = f0 +  8 * HW_;
    const float* f3 = f0 + 12 * HW_;

    unsigned long long acc[4][2];
    #pragma unroll
    for (int c = 0; c < 4; c++) { acc[c][0] = 0ull; acc[c][1] = 0ull; }

    const float4* wt4 = (const float4*)s_wt;
    int base = hlo * W_ + xi;
    int widx = (hlo - rmin) * 2 + half;

    #pragma unroll 2
    for (int row = hlo; row <= hhi; row++, base += W_, widx += 2) {
        float v0 = __ldg(f0 + base);
        float v1 = __ldg(f1 + base);
        float v2 = __ldg(f2 + base);
        float v3 = __ldg(f3 + base);
        float4 w4 = wt4[widx];           // this half's 4 bin weights
        unsigned long long wa = pack2(w4.x, w4.y);
        unsigned long long wb = pack2(w4.z, w4.w);
        unsigned long long vv0 = pack2(v0, v0);
        unsigned long long vv1 = pack2(v1, v1);
        unsigned long long vv2 = pack2(v2, v2);
        unsigned long long vv3 = pack2(v3, v3);
        fma2(acc[0][0], vv0, wa); fma2(acc[0][1], vv0, wb);
        fma2(acc[1][0], vv1, wa); fma2(acc[1][1], vv1, wb);
        fma2(acc[2][0], vv2, wa); fma2(acc[2][1], vv2, wb);
        fma2(acc[3][0], vv3, wa); fma2(acc[3][1], vv3, wb);
    }

    // Epilogue: this half's bins (4 for lo, 3 for hi), disjoint oy stores.
    int  ox      = l >> 2;
    bool doStore = (lane < 28) && ((lane & 3) == 0);
    int  oyBase  = half * 4;
    int  nBins   = half ? 3 : 4;
    float* ob    = out + ((size_t)r * C_ + ch0 + group) * (OUTK * OUTK) + ox;

    #pragma unroll
    for (int c = 0; c < 4; c++) {
        float vals[4] = { lo2(acc[c][0]), hi2(acc[c][0]),
                          lo2(acc[c][1]), hi2(acc[c][1]) };
        float* orow = ob + (size_t)(c * 4) * (OUTK * OUTK);
        #pragma unroll
        for (int b = 0; b < 4; b++) {
            if (b < nBins) {
                float v = vals[b] * xw;
                v += __shfl_xor_sync(0xffffffffu, v, 1);
                v += __shfl_xor_sync(0xffffffffu, v, 2);
                if (doStore) orow[(oyBase + b) * OUTK] = v;
            }
        }
    }
}

extern "C" void kernel_launch(void* const* d_in, const int* in_sizes, int n_in,
                              void* d_out, int out_size) {
    const float* feat = (const float*)d_in[0];
    const float* rois = (const float*)d_in[1];
    if (n_in >= 2 && in_sizes[0] == R_ * 5) {  // defensive against input order
        feat = (const float*)d_in[1];
        rois = (const float*)d_in[0];
    }
    float* out = (float*)d_out;

    dim3 grid(R_, C_ / CHUNK);   // chunk (y) slowest -> L2 phase blocking
    roialign_kernel<<<grid, 256>>>(feat, rois, out);
}

// round 12
// speedup vs baseline: 1.6514x; 1.3155x over previous
#include <cuda_runtime.h>
#include <cuda_bf16.h>

#define R_    512
#define C_    256
#define H_    200
#define W_    200
#define OUTK  7
#define HW_   (H_*W_)
#define CHUNK 64   // channels per block (grid.z = C_/CHUNK phases, z slowest)

// ---------------------------------------------------------------------------
// Grid: (7, 512, 4) = (out_y, roi, channel-chunk), z slowest -> per-phase
// feature working set (~34 MB) L2-resident (DRAM ~157 MB, compulsory).
//
// R8 skeleton (45.5 us) with one change: the two 4-channel groups are merged
// into a single load/FMA phase -- all 8 channels' row loads (up to 32 LDGs)
// issue back-to-back before the shfl/store tail, doubling per-thread MLP
// (R8 ran the groups serially: group 2's loads waited on group 1's shfl
// tail). Dense y-weights dw[4] over the contiguous row span (built once by
// warp 0) keep row-loads at rcnt<=4 per channel per oy.
//
// Lane -> (ox, x-tap): lane = ox*4 + jx; lanes 28..31 duplicate lane 27
// (same sectors), never store. Lanes {0,4,..,24} store 7 contiguous outputs.
// ---------------------------------------------------------------------------

template<int K>
__device__ __forceinline__ void accum8(
    const float* __restrict__ fb, const int off[4], const float dw[4],
    float b[8])
{
    // 8 channel pointers: c = warp + {0,8,16,24,32,40,48,56}
    float v[8][K];
    #pragma unroll
    for (int g = 0; g < 8; g++) {
        const float* f = fb + g * (8 * HW_);
        #pragma unroll
        for (int j = 0; j < K; j++)
            v[g][j] = __ldg(f + off[j]);
    }
    #pragma unroll
    for (int g = 0; g < 8; g++) {
        float a = 0.f;
        #pragma unroll
        for (int j = 0; j < K; j++)
            a += dw[j] * v[g][j];
        b[g] = a;
    }
}

__global__ __launch_bounds__(256) void roialign_kernel(
    const float* __restrict__ feat, const float* __restrict__ rois,
    float* __restrict__ out)
{
    int oy  = blockIdx.x;
    int r   = blockIdx.y;
    int ch0 = blockIdx.z * CHUNK;

    __shared__ int   s_xi[28];
    __shared__ float s_xw[28];
    __shared__ float s_dw[4];
    __shared__ int   s_rbase, s_rcnt, s_boff;

    int tid = threadIdx.x;
    if (tid < 32) {                       // warp 0, fully convergent
        const float* ro = rois + r * 5;
        bool isx = tid < 28;
        float p1 = (isx ? ro[1] : ro[2]) * 0.25f;
        float p2 = (isx ? ro[3] : ro[4]) * 0.25f;
        float bin = fmaxf(p2 - p1, 1.0f) * (1.0f / (float)OUTK);

        int o, s, tap;
        if (isx) { o = tid >> 2; s = (tid >> 1) & 1; tap = tid & 1; }
        else     { int t = tid - 28; o = oy; s = t >> 1; tap = t & 1; }

        float y = p1 + ((float)o + ((float)s + 0.5f) * 0.5f) * bin;
        bool valid = (y >= -1.0f) && (y <= 200.0f);
        float yc = fminf(fmaxf(y, 0.0f), 199.0f);
        int   yl = (int)floorf(yc);
        int   yh = min(yl + 1, 199);
        float l  = yc - (float)yl;
        float wv = tap ? l : (1.0f - l);
        if (!valid) wv = 0.0f;
        int   iv = tap ? yh : yl;

        if (isx) { s_xi[tid] = iv; s_xw[tid] = wv; }

        // Broadcast 4 y-taps (lanes 28..31); lane 0 computes dense weights.
        int   yi0 = __shfl_sync(0xffffffffu, iv, 28);
        int   yi1 = __shfl_sync(0xffffffffu, iv, 29);
        int   yi2 = __shfl_sync(0xffffffffu, iv, 30);
        int   yi3 = __shfl_sync(0xffffffffu, iv, 31);
        float yw0 = __shfl_sync(0xffffffffu, wv, 28);
        float yw1 = __shfl_sync(0xffffffffu, wv, 29);
        float yw2 = __shfl_sync(0xffffffffu, wv, 30);
        float yw3 = __shfl_sync(0xffffffffu, wv, 31);
        if (tid == 0) {
            float dw[4] = {0.f, 0.f, 0.f, 0.f};
            dw[0] += yw0;                       // yi0 == rbase (sorted taps)
            dw[yi1 - yi0] += yw1;
            dw[yi2 - yi0] += yw2;
            dw[yi3 - yi0] += yw3;
            s_dw[0] = dw[0]; s_dw[1] = dw[1];
            s_dw[2] = dw[2]; s_dw[3] = dw[3];
            s_rbase = yi0;
            s_rcnt  = yi3 - yi0 + 1;
            s_boff  = (int)ro[0] * (C_ * HW_);
        }
    }
    __syncthreads();

    int lane = tid & 31;
    int warp = tid >> 5;
    int l    = min(lane, 27);

    int   xi = s_xi[l];
    float xw = s_xw[l] * 0.25f;           // fold the S*S mean
    float dw[4] = { s_dw[0], s_dw[1], s_dw[2], s_dw[3] };
    int rbase = s_rbase;
    int rcnt  = s_rcnt;
    int off[4];
    #pragma unroll
    for (int j = 0; j < 4; j++)
        off[j] = (rbase + j) * W_ + xi;

    const float* fb = feat + s_boff + (size_t)(ch0 + warp) * HW_;

    float b[8];
    switch (rcnt) {                       // uniform per block
        case 1:  accum8<1>(fb, off, dw, b); break;
        case 2:  accum8<2>(fb, off, dw, b); break;
        case 3:  accum8<3>(fb, off, dw, b); break;
        default: accum8<4>(fb, off, dw, b); break;
    }

    // Tail: x-weight, 4-lane shfl reduce, stores for all 8 channels.
    int  ox      = l >> 2;
    bool doStore = (lane < 28) && ((lane & 3) == 0);
    float* orow  = out + (((size_t)r * C_ + ch0 + warp) * OUTK + oy) * OUTK + ox;

    #pragma unroll
    for (int g = 0; g < 8; g++) b[g] *= xw;
    #pragma unroll
    for (int g = 0; g < 8; g++) b[g] += __shfl_xor_sync(0xffffffffu, b[g], 1);
    #pragma unroll
    for (int g = 0; g < 8; g++) b[g] += __shfl_xor_sync(0xffffffffu, b[g], 2);

    if (doStore) {
        #pragma unroll
        for (int g = 0; g < 8; g++)
            orow[(size_t)(g * 8) * (OUTK * OUTK)] = b[g];
    }
}

extern "C" void kernel_launch(void* const* d_in, const int* in_sizes, int n_in,
                              void* d_out, int out_size) {
    const float* feat = (const float*)d_in[0];
    const float* rois = (const float*)d_in[1];
    if (n_in >= 2 && in_sizes[0] == R_ * 5) {  // defensive against input order
        feat = (const float*)d_in[1];
        rois = (const float*)d_in[0];
    }
    float* out = (float*)d_out;

    dim3 grid(OUTK, R_, C_ / CHUNK);
    roialign_kernel<<<grid, 256>>>(feat, rois, out);
}